// round 5
// baseline (speedup 1.0000x reference)
#include <cuda_runtime.h>
#include <cstdint>
#include <cstddef>

// Problem constants
static constexpr int kS  = 2048;
static constexpr int kB  = 2;
static constexpr int kE  = 1024;
static constexpr int kH  = 16;
static constexpr int kHD = 64;
static constexpr int kF  = 4096;
static constexpr int kL  = 4;
static constexpr int kV  = 32000;
static constexpr int kM  = kB * kS;   // 4096 token rows
static constexpr int k3E = 3 * kE;    // 3072

// ---------------------------------------------------------------------------
// Scratch (static device globals -- no allocation allowed in kernel_launch)
// ---------------------------------------------------------------------------
__device__ float g_h   [(size_t)kM * kE];    // residual stream   (16 MB)
__device__ float g_qkv [(size_t)kM * k3E];   // qkv projections   (48 MB)
__device__ float g_attn[(size_t)kM * kE];    // attention output  (16 MB)
__device__ float g_ff  [(size_t)kM * kF];    // FFN hidden        (64 MB)
__device__ float g_t   [(size_t)kM * kE];    // matmul temp       (16 MB)
__device__ int   g_is64;

// ---------------------------------------------------------------------------
// Token dtype detection: if x is int64 (little endian, values < 32000), all
// odd 32-bit words of the first 1024 tokens are zero. If x is int32, those
// words are 1024 random tokens -- all-zero has probability ~0.
// Reads only 8KB, in-bounds for both layouts. Deterministic.
// ---------------------------------------------------------------------------
__global__ void detect_x_kernel(const int* __restrict__ xw) {
  if (threadIdx.x == 0 && blockIdx.x == 0) {
    int any = 0;
    for (int i = 1; i < 2048; i += 2) any |= xw[i];
    g_is64 = (any == 0) ? 1 : 0;
  }
}

// ---------------------------------------------------------------------------
// Embedding: h[b,s,:] = word_embed[x[b,s]] + pos_embed[s]
// ---------------------------------------------------------------------------
__global__ __launch_bounds__(256) void embed_kernel(const void* __restrict__ x,
                                                    const float* __restrict__ we,
                                                    const float* __restrict__ pe) {
  const int row = blockIdx.x;            // b*S + s
  const int s = row & (kS - 1);
  const long long tok = g_is64 ? ((const long long*)x)[row]
                               : (long long)((const int*)x)[row];
  const int c = threadIdx.x * 4;
  float4 wv = *(const float4*)(we + (size_t)tok * kE + c);
  float4 pv = *(const float4*)(pe + (size_t)s * kE + c);
  float4 o;
  o.x = wv.x + pv.x; o.y = wv.y + pv.y; o.z = wv.z + pv.z; o.w = wv.w + pv.w;
  *(float4*)(g_h + (size_t)row * kE + c) = o;
}

// ---------------------------------------------------------------------------
// Tiled fp32 GEMM: C[M,N] = A[M,K] @ op(B) (+bias)(+relu)
//   TRANSB=0: B is [K,N] row-major.  TRANSB=1: B is [N,K] row-major.
//   EPI: 0 = none, 1 = +bias, 2 = relu(+bias)
// 128x128 block, BK=8, 256 threads, 8x8 per-thread microtile.
// All problem dims here are multiples of 128 (M=4096; N in {3072,1024,4096,32000};
// K in {1024,4096}), so no bounds checks.
// ---------------------------------------------------------------------------
template<int TRANSB, int EPI>
__global__ __launch_bounds__(256) void gemm_kernel(const float* __restrict__ A,
                                                   const float* __restrict__ Bm,
                                                   const float* __restrict__ bias,
                                                   float* __restrict__ C,
                                                   int M, int N, int K) {
  __shared__ float As[8][128];
  __shared__ float Bs[8][128];
  const int tid = threadIdx.x;
  const int tx = tid & 15, ty = tid >> 4;
  const int row0 = blockIdx.y * 128;
  const int col0 = blockIdx.x * 128;

  float acc[8][8];
#pragma unroll
  for (int i = 0; i < 8; i++)
#pragma unroll
    for (int j = 0; j < 8; j++) acc[i][j] = 0.f;

  const int lr  = tid >> 1;        // 0..127 (row within A/B tile)
  const int lk4 = (tid & 1) * 4;   // 0 or 4

  for (int k0 = 0; k0 < K; k0 += 8) {
    // A tile (always row-major [M,K]) -> As[k][m]
    float4 av = *(const float4*)(A + (size_t)(row0 + lr) * K + k0 + lk4);
    As[lk4 + 0][lr] = av.x;
    As[lk4 + 1][lr] = av.y;
    As[lk4 + 2][lr] = av.z;
    As[lk4 + 3][lr] = av.w;
    if (TRANSB) {
      // B is [N,K]: Bs[k][n] = B[n][k]
      float4 bv = *(const float4*)(Bm + (size_t)(col0 + lr) * K + k0 + lk4);
      Bs[lk4 + 0][lr] = bv.x;
      Bs[lk4 + 1][lr] = bv.y;
      Bs[lk4 + 2][lr] = bv.z;
      Bs[lk4 + 3][lr] = bv.w;
    } else {
      // B is [K,N]: coalesced copy
      const int bk = tid >> 5;         // 0..7
      const int bc = (tid & 31) * 4;   // 0..124
      float4 bv = *(const float4*)(Bm + (size_t)(k0 + bk) * N + col0 + bc);
      *(float4*)&Bs[bk][bc] = bv;
    }
    __syncthreads();
#pragma unroll
    for (int kk = 0; kk < 8; kk++) {
      float a[8], b[8];
      *(float4*)&a[0] = *(const float4*)&As[kk][ty * 8];
      *(float4*)&a[4] = *(const float4*)&As[kk][ty * 8 + 4];
      *(float4*)&b[0] = *(const float4*)&Bs[kk][tx * 8];
      *(float4*)&b[4] = *(const float4*)&Bs[kk][tx * 8 + 4];
#pragma unroll
      for (int i = 0; i < 8; i++)
#pragma unroll
        for (int j = 0; j < 8; j++)
          acc[i][j] += a[i] * b[j];
    }
    __syncthreads();
  }

#pragma unroll
  for (int i = 0; i < 8; i++) {
    const size_t roff = (size_t)(row0 + ty * 8 + i) * N + col0 + tx * 8;
#pragma unroll
    for (int j4 = 0; j4 < 8; j4 += 4) {
      float4 o;
      float* po = &o.x;
#pragma unroll
      for (int j = 0; j < 4; j++) {
        float v = acc[i][j4 + j];
        if (EPI >= 1) v += bias[col0 + tx * 8 + j4 + j];
        if (EPI == 2) v = fmaxf(v, 0.f);
        po[j] = v;
      }
      *(float4*)(C + roff + j4) = o;
    }
  }
}

// ---------------------------------------------------------------------------
// Causal flash attention, fp32.
// grid = (S/64, H, B), 256 threads (8 warps). Each block owns a 64-row q-tile
// of one (b,h) and streams k-tiles of 64 with online softmax.
// qkv layout along 3E axis: h*192 + c*64 + d, c=0:K 1:Q 2:V.
// Output layout: attn[b,s, h*64+d].
// Per warp: 8 q rows; lane owns score columns {lane, lane+32} and output dims
// {lane, lane+32}. K stored transposed in smem (Ks[d][c]) -> conflict-free.
// Dynamic smem: Qs 16K + Ks 16K + Vs 16K + Ps 16K = 64KB.
// ---------------------------------------------------------------------------
__global__ __launch_bounds__(256) void attn_kernel(const float* __restrict__ qkv,
                                                   float* __restrict__ out) {
  extern __shared__ float sm[];
  float* Qs = sm;            // [64][64]  Qs[r][d]
  float* Ks = sm + 4096;     // [64][64]  Ks[d][c]
  float* Vs = sm + 8192;     // [64][64]  Vs[c][d]
  float* Ps = sm + 12288;    // [8 warps][8][64]

  const int qt  = blockIdx.x;
  const int h   = blockIdx.y;
  const int b   = blockIdx.z;
  const int tid = threadIdx.x;
  const int w = tid >> 5, lane = tid & 31;

  const size_t rowb = (size_t)b * kS;
  const int    hoff = h * (3 * kHD);   // within a qkv row

  // Q tile (c=1 slice)
  for (int idx = tid; idx < 1024; idx += 256) {
    int r  = idx >> 4;
    int d4 = (idx & 15) << 2;
    float4 v = *(const float4*)(qkv + (rowb + qt * 64 + r) * k3E + hoff + 64 + d4);
    *(float4*)&Qs[r * 64 + d4] = v;
  }

  float o0[8], o1[8], mrow[8], lrow[8];
#pragma unroll
  for (int r = 0; r < 8; r++) { o0[r] = 0.f; o1[r] = 0.f; mrow[r] = -1e30f; lrow[r] = 0.f; }

  const int q0 = qt * 64 + w * 8;
  float* Pw = Ps + w * 512;

  for (int kt = 0; kt <= qt; kt++) {
    __syncthreads();   // previous tile fully consumed; also orders Qs for kt=0
    // load K (transposed) and V tiles
    for (int idx = tid; idx < 1024; idx += 256) {
      int c  = idx >> 4;
      int d4 = (idx & 15) << 2;
      const float* src = qkv + (rowb + kt * 64 + c) * k3E + hoff + d4;
      float4 kv = *(const float4*)(src);          // c=0 slice (K)
      Ks[(d4 + 0) * 64 + c] = kv.x;
      Ks[(d4 + 1) * 64 + c] = kv.y;
      Ks[(d4 + 2) * 64 + c] = kv.z;
      Ks[(d4 + 3) * 64 + c] = kv.w;
      float4 vv = *(const float4*)(src + 128);    // c=2 slice (V)
      *(float4*)&Vs[c * 64 + d4] = vv;
    }
    __syncthreads();

    const bool diag = (kt == qt);
#pragma unroll 1
    for (int r = 0; r < 8; r++) {
      float s0 = 0.f, s1 = 0.f;
      const float* qr = Qs + (w * 8 + r) * 64;
#pragma unroll
      for (int d = 0; d < 64; d++) {
        float q = qr[d];
        s0 += q * Ks[d * 64 + lane];
        s1 += q * Ks[d * 64 + lane + 32];
      }
      s0 *= 0.125f; s1 *= 0.125f;          // 1/sqrt(64)
      if (diag) {
        const int qg = q0 + r;
        if (kt * 64 + lane      > qg) s0 = -1e30f;
        if (kt * 64 + lane + 32 > qg) s1 = -1e30f;
      }
      float mx = fmaxf(s0, s1);
#pragma unroll
      for (int off = 16; off; off >>= 1) mx = fmaxf(mx, __shfl_xor_sync(0xffffffffu, mx, off));
      const float mnew = fmaxf(mrow[r], mx);
      const float p0 = __expf(s0 - mnew);
      const float p1 = __expf(s1 - mnew);
      float rs = p0 + p1;
#pragma unroll
      for (int off = 16; off; off >>= 1) rs += __shfl_xor_sync(0xffffffffu, rs, off);
      const float corr = __expf(mrow[r] - mnew);
      mrow[r] = mnew;
      lrow[r] = lrow[r] * corr + rs;
      o0[r] *= corr; o1[r] *= corr;
      Pw[r * 64 + lane]      = p0;
      Pw[r * 64 + lane + 32] = p1;
      __syncwarp();
#pragma unroll 8
      for (int c = 0; c < 64; c++) {
        const float p = Pw[r * 64 + c];
        o0[r] += p * Vs[c * 64 + lane];
        o1[r] += p * Vs[c * 64 + lane + 32];
      }
      __syncwarp();
    }
  }

#pragma unroll
  for (int r = 0; r < 8; r++) {
    const float inv = 1.f / lrow[r];
    const int sg = q0 + r;
    const size_t o = (rowb + sg) * kE + h * kHD;
    out[o + lane]      = o0[r] * inv;
    out[o + lane + 32] = o1[r] * inv;
  }
}

// ---------------------------------------------------------------------------
// Fused LayerNorm + residual: h[row] = LN(x[row])*g + b + h[row]
// One block (256 threads) per row of 1024.
// ---------------------------------------------------------------------------
__global__ __launch_bounds__(256) void ln_add_kernel(const float* __restrict__ x,
                                                     const float* __restrict__ gamma,
                                                     const float* __restrict__ beta,
                                                     float* __restrict__ h) {
  __shared__ float rs[8], rs2[8];
  const int row = blockIdx.x;
  const int tid = threadIdx.x;
  const int c = tid * 4;
  const size_t off = (size_t)row * kE + c;
  float4 xv = *(const float4*)(x + off);
  float s  = xv.x + xv.y + xv.z + xv.w;
  float s2 = xv.x * xv.x + xv.y * xv.y + xv.z * xv.z + xv.w * xv.w;
#pragma unroll
  for (int o = 16; o; o >>= 1) {
    s  += __shfl_xor_sync(0xffffffffu, s,  o);
    s2 += __shfl_xor_sync(0xffffffffu, s2, o);
  }
  if ((tid & 31) == 0) { rs[tid >> 5] = s; rs2[tid >> 5] = s2; }
  __syncthreads();
  float ts = 0.f, ts2 = 0.f;
#pragma unroll
  for (int i = 0; i < 8; i++) { ts += rs[i]; ts2 += rs2[i]; }
  const float mean = ts * (1.f / kE);
  const float var  = ts2 * (1.f / kE) - mean * mean;
  const float rstd = rsqrtf(var + 1e-6f);
  float4 hv = *(const float4*)(h + off);
  float4 gv = *(const float4*)(gamma + c);
  float4 bv = *(const float4*)(beta + c);
  float4 o4;
  o4.x = (xv.x - mean) * rstd * gv.x + bv.x + hv.x;
  o4.y = (xv.y - mean) * rstd * gv.y + bv.y + hv.y;
  o4.z = (xv.z - mean) * rstd * gv.z + bv.z + hv.z;
  o4.w = (xv.w - mean) * rstd * gv.w + bv.w + hv.w;
  *(float4*)(h + off) = o4;
}

// ---------------------------------------------------------------------------
// Launcher
// ---------------------------------------------------------------------------
extern "C" void kernel_launch(void* const* d_in, const int* in_sizes, int n_in,
                              void* d_out, int out_size) {
  (void)in_sizes; (void)n_in; (void)out_size;
  const void*  x   = d_in[0];
  const float* we  = (const float*)d_in[1];
  const float* pe  = (const float*)d_in[2];
  const float* KQV = (const float*)d_in[3];
  const float* WO  = (const float*)d_in[4];
  const float* Wup = (const float*)d_in[5];
  const float* bup = (const float*)d_in[6];
  const float* Wdn = (const float*)d_in[7];
  const float* bdn = (const float*)d_in[8];
  const float* g1  = (const float*)d_in[9];
  const float* b1  = (const float*)d_in[10];
  const float* g2  = (const float*)d_in[11];
  const float* b2  = (const float*)d_in[12];
  const float* ub  = (const float*)d_in[13];
  float* out = (float*)d_out;

  float *h, *qkvb, *attnb, *ffb, *tb;
  cudaGetSymbolAddress((void**)&h,     g_h);
  cudaGetSymbolAddress((void**)&qkvb,  g_qkv);
  cudaGetSymbolAddress((void**)&attnb, g_attn);
  cudaGetSymbolAddress((void**)&ffb,   g_ff);
  cudaGetSymbolAddress((void**)&tb,    g_t);

  cudaFuncSetAttribute(attn_kernel, cudaFuncAttributeMaxDynamicSharedMemorySize, 64 * 1024);

  detect_x_kernel<<<1, 32>>>((const int*)x);
  embed_kernel<<<kM, 256>>>(x, we, pe);

  for (int l = 0; l < kL; l++) {
    // qkv = h @ KQV[l]
    gemm_kernel<0, 0><<<dim3(k3E / 128, kM / 128), 256>>>(
        h, KQV + (size_t)l * kE * k3E, nullptr, qkvb, kM, k3E, kE);
    // attention
    attn_kernel<<<dim3(kS / 64, kH, kB), 256, 64 * 1024>>>(qkvb, attnb);
    // t = attn @ WO[l]
    gemm_kernel<0, 0><<<dim3(kE / 128, kM / 128), 256>>>(
        attnb, WO + (size_t)l * kE * kE, nullptr, tb, kM, kE, kE);
    // h = LN(t) + h
    ln_add_kernel<<<kM, 256>>>(tb, g1 + l * kE, b1 + l * kE, h);
    // ff = relu(h @ Wup[l] + bup[l])
    gemm_kernel<0, 2><<<dim3(kF / 128, kM / 128), 256>>>(
        h, Wup + (size_t)l * kE * kF, bup + (size_t)l * kF, ffb, kM, kF, kE);
    // t = ff @ Wdn[l] + bdn[l]
    gemm_kernel<0, 1><<<dim3(kE / 128, kM / 128), 256>>>(
        ffb, Wdn + (size_t)l * kF * kE, bdn + (size_t)l * kE, tb, kM, kE, kF);
    // h = LN(t) + h
    ln_add_kernel<<<kM, 256>>>(tb, g2 + l * kE, b2 + l * kE, h);
  }

  // logits = h @ word_embed^T + unembed_b   (B transposed: [V,E])
  gemm_kernel<1, 1><<<dim3(kV / 128, kM / 128), 256>>>(
      h, we, ub, out, kM, kV, kE);
}

// round 6
// speedup vs baseline: 1.6394x; 1.6394x over previous
#include <cuda_runtime.h>
#include <cstdint>
#include <cstddef>

// Problem constants
static constexpr int kS  = 2048;
static constexpr int kB  = 2;
static constexpr int kE  = 1024;
static constexpr int kH  = 16;
static constexpr int kHD = 64;
static constexpr int kF  = 4096;
static constexpr int kL  = 4;
static constexpr int kV  = 32000;
static constexpr int kM  = kB * kS;   // 4096 token rows
static constexpr int k3E = 3 * kE;    // 3072

// ---------------------------------------------------------------------------
// Scratch (static device globals -- no allocation allowed in kernel_launch)
// ---------------------------------------------------------------------------
__device__ float g_h   [(size_t)kM * kE];    // residual stream   (16 MB)
__device__ float g_qkv [(size_t)kM * k3E];   // qkv projections   (48 MB)
__device__ float g_attn[(size_t)kM * kE];    // attention output  (16 MB)
__device__ float g_ff  [(size_t)kM * kF];    // FFN hidden        (64 MB)
__device__ float g_t   [(size_t)kM * kE];    // matmul temp       (16 MB)
__device__ int   g_is64;

// ---------------------------------------------------------------------------
// Token dtype detection: if x is int64 (little endian, values < 32000), all
// odd 32-bit words of the first 1024 tokens are zero. If x is int32, those
// words are 1024 random tokens -- all-zero has probability ~0.
// Reads only 8KB, in-bounds for both layouts. Deterministic.
// ---------------------------------------------------------------------------
__global__ void detect_x_kernel(const int* __restrict__ xw) {
  if (threadIdx.x == 0 && blockIdx.x == 0) {
    int any = 0;
    for (int i = 1; i < 2048; i += 2) any |= xw[i];
    g_is64 = (any == 0) ? 1 : 0;
  }
}

// ---------------------------------------------------------------------------
// Embedding: h[b,s,:] = word_embed[x[b,s]] + pos_embed[s]
// ---------------------------------------------------------------------------
__global__ __launch_bounds__(256) void embed_kernel(const void* __restrict__ x,
                                                    const float* __restrict__ we,
                                                    const float* __restrict__ pe) {
  const int row = blockIdx.x;            // b*S + s
  const int s = row & (kS - 1);
  const long long tok = g_is64 ? ((const long long*)x)[row]
                               : (long long)((const int*)x)[row];
  const int c = threadIdx.x * 4;
  float4 wv = *(const float4*)(we + (size_t)tok * kE + c);
  float4 pv = *(const float4*)(pe + (size_t)s * kE + c);
  float4 o;
  o.x = wv.x + pv.x; o.y = wv.y + pv.y; o.z = wv.z + pv.z; o.w = wv.w + pv.w;
  *(float4*)(g_h + (size_t)row * kE + c) = o;
}

// ---------------------------------------------------------------------------
// Tiled fp32 GEMM: C[M,N] = A[M,K] @ op(B) (+bias)(+relu)
//   TRANSB=0: B is [K,N] row-major.  TRANSB=1: B is [N,K] row-major.
//   EPI: 0 = none, 1 = +bias, 2 = relu(+bias)
// 128x128 block, BK=8, 256 threads, 8x8 per-thread microtile.
// All problem dims here are multiples of 128 (M=4096; N in {3072,1024,4096,32000};
// K in {1024,4096}), so no bounds checks.
// ---------------------------------------------------------------------------
template<int TRANSB, int EPI>
__global__ __launch_bounds__(256) void gemm_kernel(const float* __restrict__ A,
                                                   const float* __restrict__ Bm,
                                                   const float* __restrict__ bias,
                                                   float* __restrict__ C,
                                                   int M, int N, int K) {
  __shared__ float As[8][128];
  __shared__ float Bs[8][128];
  const int tid = threadIdx.x;
  const int tx = tid & 15, ty = tid >> 4;
  const int row0 = blockIdx.y * 128;
  const int col0 = blockIdx.x * 128;

  float acc[8][8];
#pragma unroll
  for (int i = 0; i < 8; i++)
#pragma unroll
    for (int j = 0; j < 8; j++) acc[i][j] = 0.f;

  const int lr  = tid >> 1;        // 0..127 (row within A/B tile)
  const int lk4 = (tid & 1) * 4;   // 0 or 4

  for (int k0 = 0; k0 < K; k0 += 8) {
    // A tile (always row-major [M,K]) -> As[k][m]
    float4 av = *(const float4*)(A + (size_t)(row0 + lr) * K + k0 + lk4);
    As[lk4 + 0][lr] = av.x;
    As[lk4 + 1][lr] = av.y;
    As[lk4 + 2][lr] = av.z;
    As[lk4 + 3][lr] = av.w;
    if (TRANSB) {
      // B is [N,K]: Bs[k][n] = B[n][k]
      float4 bv = *(const float4*)(Bm + (size_t)(col0 + lr) * K + k0 + lk4);
      Bs[lk4 + 0][lr] = bv.x;
      Bs[lk4 + 1][lr] = bv.y;
      Bs[lk4 + 2][lr] = bv.z;
      Bs[lk4 + 3][lr] = bv.w;
    } else {
      // B is [K,N]: coalesced copy
      const int bk = tid >> 5;         // 0..7
      const int bc = (tid & 31) * 4;   // 0..124
      float4 bv = *(const float4*)(Bm + (size_t)(k0 + bk) * N + col0 + bc);
      *(float4*)&Bs[bk][bc] = bv;
    }
    __syncthreads();
#pragma unroll
    for (int kk = 0; kk < 8; kk++) {
      float a[8], b[8];
      *(float4*)&a[0] = *(const float4*)&As[kk][ty * 8];
      *(float4*)&a[4] = *(const float4*)&As[kk][ty * 8 + 4];
      *(float4*)&b[0] = *(const float4*)&Bs[kk][tx * 8];
      *(float4*)&b[4] = *(const float4*)&Bs[kk][tx * 8 + 4];
#pragma unroll
      for (int i = 0; i < 8; i++)
#pragma unroll
        for (int j = 0; j < 8; j++)
          acc[i][j] += a[i] * b[j];
    }
    __syncthreads();
  }

#pragma unroll
  for (int i = 0; i < 8; i++) {
    const size_t roff = (size_t)(row0 + ty * 8 + i) * N + col0 + tx * 8;
#pragma unroll
    for (int j4 = 0; j4 < 8; j4 += 4) {
      float4 o;
      float* po = &o.x;
#pragma unroll
      for (int j = 0; j < 4; j++) {
        float v = acc[i][j4 + j];
        if (EPI >= 1) v += bias[col0 + tx * 8 + j4 + j];
        if (EPI == 2) v = fmaxf(v, 0.f);
        po[j] = v;
      }
      *(float4*)(C + roff + j4) = o;
    }
  }
}

// ---------------------------------------------------------------------------
// Causal flash attention, fp32.
// grid = (S/64, H, B), 256 threads (8 warps). Each block owns a 64-row q-tile
// of one (b,h) and streams k-tiles of 64 with online softmax.
// qkv layout along 3E axis: h*192 + c*64 + d, c=0:K 1:Q 2:V.
// Output layout: attn[b,s, h*64+d].
// Per warp: 8 q rows; lane owns score columns {lane, lane+32} and output dims
// {lane, lane+32}. K stored transposed in smem (Ks[d][c]) -> conflict-free.
// Dynamic smem: Qs 16K + Ks 16K + Vs 16K + Ps 16K = 64KB.
// ---------------------------------------------------------------------------
__global__ __launch_bounds__(256) void attn_kernel(const float* __restrict__ qkv,
                                                   float* __restrict__ out) {
  extern __shared__ float sm[];
  float* Qs = sm;            // [64][64]  Qs[r][d]
  float* Ks = sm + 4096;     // [64][64]  Ks[d][c]
  float* Vs = sm + 8192;     // [64][64]  Vs[c][d]
  float* Ps = sm + 12288;    // [8 warps][8][64]

  const int qt  = blockIdx.x;
  const int h   = blockIdx.y;
  const int b   = blockIdx.z;
  const int tid = threadIdx.x;
  const int w = tid >> 5, lane = tid & 31;

  const size_t rowb = (size_t)b * kS;
  const int    hoff = h * (3 * kHD);   // within a qkv row

  // Q tile (c=1 slice)
  for (int idx = tid; idx < 1024; idx += 256) {
    int r  = idx >> 4;
    int d4 = (idx & 15) << 2;
    float4 v = *(const float4*)(qkv + (rowb + qt * 64 + r) * k3E + hoff + 64 + d4);
    *(float4*)&Qs[r * 64 + d4] = v;
  }

  float o0[8], o1[8], mrow[8], lrow[8];
#pragma unroll
  for (int r = 0; r < 8; r++) { o0[r] = 0.f; o1[r] = 0.f; mrow[r] = -1e30f; lrow[r] = 0.f; }

  const int q0 = qt * 64 + w * 8;
  float* Pw = Ps + w * 512;

  for (int kt = 0; kt <= qt; kt++) {
    __syncthreads();   // previous tile fully consumed; also orders Qs for kt=0
    // load K (transposed) and V tiles
    for (int idx = tid; idx < 1024; idx += 256) {
      int c  = idx >> 4;
      int d4 = (idx & 15) << 2;
      const float* src = qkv + (rowb + kt * 64 + c) * k3E + hoff + d4;
      float4 kv = *(const float4*)(src);          // c=0 slice (K)
      Ks[(d4 + 0) * 64 + c] = kv.x;
      Ks[(d4 + 1) * 64 + c] = kv.y;
      Ks[(d4 + 2) * 64 + c] = kv.z;
      Ks[(d4 + 3) * 64 + c] = kv.w;
      float4 vv = *(const float4*)(src + 128);    // c=2 slice (V)
      *(float4*)&Vs[c * 64 + d4] = vv;
    }
    __syncthreads();

    const bool diag = (kt == qt);
#pragma unroll 1
    for (int r = 0; r < 8; r++) {
      float s0 = 0.f, s1 = 0.f;
      const float* qr = Qs + (w * 8 + r) * 64;
#pragma unroll
      for (int d = 0; d < 64; d++) {
        float q = qr[d];
        s0 += q * Ks[d * 64 + lane];
        s1 += q * Ks[d * 64 + lane + 32];
      }
      s0 *= 0.125f; s1 *= 0.125f;          // 1/sqrt(64)
      if (diag) {
        const int qg = q0 + r;
        if (kt * 64 + lane      > qg) s0 = -1e30f;
        if (kt * 64 + lane + 32 > qg) s1 = -1e30f;
      }
      float mx = fmaxf(s0, s1);
#pragma unroll
      for (int off = 16; off; off >>= 1) mx = fmaxf(mx, __shfl_xor_sync(0xffffffffu, mx, off));
      const float mnew = fmaxf(mrow[r], mx);
      const float p0 = __expf(s0 - mnew);
      const float p1 = __expf(s1 - mnew);
      float rs = p0 + p1;
#pragma unroll
      for (int off = 16; off; off >>= 1) rs += __shfl_xor_sync(0xffffffffu, rs, off);
      const float corr = __expf(mrow[r] - mnew);
      mrow[r] = mnew;
      lrow[r] = lrow[r] * corr + rs;
      o0[r] *= corr; o1[r] *= corr;
      Pw[r * 64 + lane]      = p0;
      Pw[r * 64 + lane + 32] = p1;
      __syncwarp();
#pragma unroll 8
      for (int c = 0; c < 64; c++) {
        const float p = Pw[r * 64 + c];
        o0[r] += p * Vs[c * 64 + lane];
        o1[r] += p * Vs[c * 64 + lane + 32];
      }
      __syncwarp();
    }
  }

#pragma unroll
  for (int r = 0; r < 8; r++) {
    const float inv = 1.f / lrow[r];
    const int sg = q0 + r;
    const size_t o = (rowb + sg) * kE + h * kHD;
    out[o + lane]      = o0[r] * inv;
    out[o + lane + 32] = o1[r] * inv;
  }
}

// ---------------------------------------------------------------------------
// Fused LayerNorm + residual: h[row] = LN(x[row])*g + b + h[row]
// One block (256 threads) per row of 1024.
// ---------------------------------------------------------------------------
__global__ __launch_bounds__(256) void ln_add_kernel(const float* __restrict__ x,
                                                     const float* __restrict__ gamma,
                                                     const float* __restrict__ beta,
                                                     float* __restrict__ h) {
  __shared__ float rs[8], rs2[8];
  const int row = blockIdx.x;
  const int tid = threadIdx.x;
  const int c = tid * 4;
  const size_t off = (size_t)row * kE + c;
  float4 xv = *(const float4*)(x + off);
  float s  = xv.x + xv.y + xv.z + xv.w;
  float s2 = xv.x * xv.x + xv.y * xv.y + xv.z * xv.z + xv.w * xv.w;
#pragma unroll
  for (int o = 16; o; o >>= 1) {
    s  += __shfl_xor_sync(0xffffffffu, s,  o);
    s2 += __shfl_xor_sync(0xffffffffu, s2, o);
  }
  if ((tid & 31) == 0) { rs[tid >> 5] = s; rs2[tid >> 5] = s2; }
  __syncthreads();
  float ts = 0.f, ts2 = 0.f;
#pragma unroll
  for (int i = 0; i < 8; i++) { ts += rs[i]; ts2 += rs2[i]; }
  const float mean = ts * (1.f / kE);
  const float var  = ts2 * (1.f / kE) - mean * mean;
  const float rstd = rsqrtf(var + 1e-6f);
  float4 hv = *(const float4*)(h + off);
  float4 gv = *(const float4*)(gamma + c);
  float4 bv = *(const float4*)(beta + c);
  float4 o4;
  o4.x = (xv.x - mean) * rstd * gv.x + bv.x + hv.x;
  o4.y = (xv.y - mean) * rstd * gv.y + bv.y + hv.y;
  o4.z = (xv.z - mean) * rstd * gv.z + bv.z + hv.z;
  o4.w = (xv.w - mean) * rstd * gv.w + bv.w + hv.w;
  *(float4*)(h + off) = o4;
}

// ---------------------------------------------------------------------------
// Launcher
// ---------------------------------------------------------------------------
extern "C" void kernel_launch(void* const* d_in, const int* in_sizes, int n_in,
                              void* d_out, int out_size) {
  (void)in_sizes; (void)n_in; (void)out_size;
  const void*  x   = d_in[0];
  const float* we  = (const float*)d_in[1];
  const float* pe  = (const float*)d_in[2];
  const float* KQV = (const float*)d_in[3];
  const float* WO  = (const float*)d_in[4];
  const float* Wup = (const float*)d_in[5];
  const float* bup = (const float*)d_in[6];
  const float* Wdn = (const float*)d_in[7];
  const float* bdn = (const float*)d_in[8];
  const float* g1  = (const float*)d_in[9];
  const float* b1  = (const float*)d_in[10];
  const float* g2  = (const float*)d_in[11];
  const float* b2  = (const float*)d_in[12];
  const float* ub  = (const float*)d_in[13];
  float* out = (float*)d_out;

  float *h, *qkvb, *attnb, *ffb, *tb;
  cudaGetSymbolAddress((void**)&h,     g_h);
  cudaGetSymbolAddress((void**)&qkvb,  g_qkv);
  cudaGetSymbolAddress((void**)&attnb, g_attn);
  cudaGetSymbolAddress((void**)&ffb,   g_ff);
  cudaGetSymbolAddress((void**)&tb,    g_t);

  cudaFuncSetAttribute(attn_kernel, cudaFuncAttributeMaxDynamicSharedMemorySize, 64 * 1024);

  detect_x_kernel<<<1, 32>>>((const int*)x);
  embed_kernel<<<kM, 256>>>(x, we, pe);

  for (int l = 0; l < kL; l++) {
    // qkv = h @ KQV[l]
    gemm_kernel<0, 0><<<dim3(k3E / 128, kM / 128), 256>>>(
        h, KQV + (size_t)l * kE * k3E, nullptr, qkvb, kM, k3E, kE);
    // attention
    attn_kernel<<<dim3(kS / 64, kH, kB), 256, 64 * 1024>>>(qkvb, attnb);
    // t = attn @ WO[l]
    gemm_kernel<0, 0><<<dim3(kE / 128, kM / 128), 256>>>(
        attnb, WO + (size_t)l * kE * kE, nullptr, tb, kM, kE, kE);
    // h = LN(t) + h
    ln_add_kernel<<<kM, 256>>>(tb, g1 + l * kE, b1 + l * kE, h);
    // ff = relu(h @ Wup[l] + bup[l])
    gemm_kernel<0, 2><<<dim3(kF / 128, kM / 128), 256>>>(
        h, Wup + (size_t)l * kE * kF, bup + (size_t)l * kF, ffb, kM, kF, kE);
    // t = ff @ Wdn[l] + bdn[l]
    gemm_kernel<0, 1><<<dim3(kE / 128, kM / 128), 256>>>(
        ffb, Wdn + (size_t)l * kF * kE, bdn + (size_t)l * kE, tb, kM, kE, kF);
    // h = LN(t) + h
    ln_add_kernel<<<kM, 256>>>(tb, g2 + l * kE, b2 + l * kE, h);
  }

  // logits = h @ word_embed^T + unembed_b   (B transposed: [V,E])
  gemm_kernel<1, 1><<<dim3(kV / 128, kM / 128), 256>>>(
      h, we, ub, out, kM, kV, kE);
}

// round 12
// speedup vs baseline: 3.1014x; 1.8918x over previous
#include <cuda_runtime.h>
#include <cuda_bf16.h>
#include <cstdint>
#include <cstddef>

static constexpr int kS = 2048, kB = 2, kE = 1024, kH = 16, kHD = 64;
static constexpr int kF = 4096, kL = 4, kV = 32000;
static constexpr int kM = kB * kS;     // 4096
static constexpr int k3E = 3 * kE;     // 3072

// ---------------- scratch (no allocs allowed) ----------------
__device__ float g_h  [(size_t)kM * kE];
__device__ float g_qkv[(size_t)kM * k3E];
__device__ float g_t  [(size_t)kM * kE];
__device__ __nv_bfloat16 g_hP   [2 * (size_t)kM * kE];
__device__ __nv_bfloat16 g_attnP[2 * (size_t)kM * kE];
__device__ __nv_bfloat16 g_ffP  [2 * (size_t)kM * kF];
__device__ __nv_bfloat16 g_wKQV [(size_t)kL * 2 * k3E * kE];
__device__ __nv_bfloat16 g_wWO  [(size_t)kL * 2 * kE  * kE];
__device__ __nv_bfloat16 g_wUp  [(size_t)kL * 2 * kF  * kE];
__device__ __nv_bfloat16 g_wDn  [(size_t)kL * 2 * kE  * kF];
__device__ __nv_bfloat16 g_wWE  [2 * (size_t)kV * kE];
__device__ int g_is64;

// ---------------- helpers (baseline PTX only: sm_80-level, no 'a' features) ----
__device__ __forceinline__ uint32_t smem_u32(const void* p) {
  uint32_t a;
  asm("{ .reg .u64 t; cvta.to.shared.u64 t, %1; cvt.u32.u64 %0, t; }" : "=r"(a) : "l"(p));
  return a;
}
#define CP_ASYNC16(d, s) \
  asm volatile("cp.async.cg.shared.global [%0], [%1], 16;" :: "r"(d), "l"(s) : "memory")
#define CP_COMMIT() asm volatile("cp.async.commit_group;" ::: "memory")
#define LDSM4(r0, r1, r2, r3, a) \
  asm volatile("ldmatrix.sync.aligned.m8n8.x4.shared.b16 {%0,%1,%2,%3},[%4];" \
               : "=r"(r0), "=r"(r1), "=r"(r2), "=r"(r3) : "r"(a))
#define MMA16816(c, a0, a1, a2, a3, b0, b1) \
  asm volatile("mma.sync.aligned.m16n8k16.row.col.f32.bf16.bf16.f32 " \
               "{%0,%1,%2,%3},{%4,%5,%6,%7},{%8,%9},{%0,%1,%2,%3};" \
               : "+f"((c)[0]), "+f"((c)[1]), "+f"((c)[2]), "+f"((c)[3]) \
               : "r"(a0), "r"(a1), "r"(a2), "r"(a3), "r"(b0), "r"(b1))

__device__ __forceinline__ void split2(float v, __nv_bfloat16& h, __nv_bfloat16& l) {
  h = __float2bfloat16(v);
  l = __float2bfloat16(v - __bfloat162float(h));
}
__device__ __forceinline__ uint32_t packb(__nv_bfloat16 a, __nv_bfloat16 b) {
  return (uint32_t)__bfloat16_as_ushort(a) | ((uint32_t)__bfloat16_as_ushort(b) << 16);
}

// ---------------- token dtype detect ----------------
__global__ void detect_x_kernel(const int* __restrict__ xw) {
  if (threadIdx.x == 0 && blockIdx.x == 0) {
    int any = 0;
    for (int i = 1; i < 2048; i += 2) any |= xw[i];
    g_is64 = (any == 0) ? 1 : 0;
  }
}

// ---------------- weight prep ----------------
// transpose+split: dst[z][plane][n][k] = split(src[z][k][n])
__global__ __launch_bounds__(256) void wsplitT_kernel(const float* __restrict__ src,
                                                      __nv_bfloat16* __restrict__ dst,
                                                      int Kd, int Nd) {
  __shared__ float t[32][33];
  const size_t lsz = (size_t)Kd * Nd;
  const float* S = src + (size_t)blockIdx.z * lsz;
  __nv_bfloat16* Hh = dst + (size_t)blockIdx.z * 2 * lsz;
  __nv_bfloat16* Ll = Hh + lsz;
  const int k0 = blockIdx.y * 32, n0 = blockIdx.x * 32;
  const int tx = threadIdx.x & 31, ty = threadIdx.x >> 5;
#pragma unroll
  for (int i = 0; i < 32; i += 8)
    t[ty + i][tx] = S[(size_t)(k0 + ty + i) * Nd + n0 + tx];
  __syncthreads();
#pragma unroll
  for (int i = 0; i < 32; i += 8) {
    float v = t[tx][ty + i];
    __nv_bfloat16 h, l; split2(v, h, l);
    size_t o = (size_t)(n0 + ty + i) * Kd + k0 + tx;
    Hh[o] = h; Ll[o] = l;
  }
}
// elementwise split (word_embed is already [V,E] = [N,K])
__global__ __launch_bounds__(256) void wsplit_kernel(const float* __restrict__ s,
                                                     __nv_bfloat16* __restrict__ d, size_t n) {
  size_t i = ((size_t)blockIdx.x * 256 + threadIdx.x) * 4;
  if (i >= n) return;
  float4 v = *(const float4*)(s + i);
  __nv_bfloat16 h0,h1,h2,h3,l0,l1,l2,l3;
  split2(v.x,h0,l0); split2(v.y,h1,l1); split2(v.z,h2,l2); split2(v.w,h3,l3);
  uint2 hp; hp.x = packb(h0,h1); hp.y = packb(h2,h3);
  uint2 lp; lp.x = packb(l0,l1); lp.y = packb(l2,l3);
  *(uint2*)(d + i) = hp;
  *(uint2*)(d + n + i) = lp;
}

// ---------------- embedding (fp32 + planes) ----------------
__global__ __launch_bounds__(256) void embed_kernel(const void* __restrict__ x,
                                                    const float* __restrict__ we,
                                                    const float* __restrict__ pe) {
  const int row = blockIdx.x;
  const int s = row & (kS - 1);
  const long long tok = g_is64 ? ((const long long*)x)[row] : (long long)((const int*)x)[row];
  const int c = threadIdx.x * 4;
  float4 wv = *(const float4*)(we + (size_t)tok * kE + c);
  float4 pv = *(const float4*)(pe + (size_t)s * kE + c);
  float4 o;
  o.x = wv.x + pv.x; o.y = wv.y + pv.y; o.z = wv.z + pv.z; o.w = wv.w + pv.w;
  const size_t off = (size_t)row * kE + c;
  *(float4*)(g_h + off) = o;
  __nv_bfloat16 h0,h1,h2,h3,l0,l1,l2,l3;
  split2(o.x,h0,l0); split2(o.y,h1,l1); split2(o.z,h2,l2); split2(o.w,h3,l3);
  uint2 hp; hp.x = packb(h0,h1); hp.y = packb(h2,h3);
  uint2 lp; lp.x = packb(l0,l1); lp.y = packb(l2,l3);
  *(uint2*)(g_hP + off) = hp;
  *(uint2*)(g_hP + (size_t)kM * kE + off) = lp;
}

// ---------------- warp-MMA GEMM (bf16x2-split, 3-term, fp32 acc) ----------------
// C[M,N] = (Ah+Al)[M,K] @ (Bh+Bl)[N,K]^T
// 128x128 CTA tile, 8 warps (2m x 4n), warp tile 64x32, K-chunk 64, cp.async x2.
// Smem per buffer: Ah(16K) Al(16K) Bh(16K) Bl(16K); rows of 128B, chunk-XOR swizzle.
static constexpr int SMEM_MM = 2 * 65536;

__device__ __forceinline__ void issue_chunk(uint32_t sb, int b,
                                            const __nv_bfloat16* __restrict__ Ah,
                                            const __nv_bfloat16* __restrict__ Al,
                                            const __nv_bfloat16* __restrict__ Bh,
                                            const __nv_bfloat16* __restrict__ Bl,
                                            int row0, int col0, int k0, int K, int tid) {
#pragma unroll
  for (int i = 0; i < 16; i++) {
    int g = tid + i * 256;          // 0..4095
    int pl = g >> 10;               // 0:Ah 1:Al 2:Bh 3:Bl
    int j = g & 1023;
    int r = j >> 3, c = j & 7;      // row 0..127, 16B-chunk 0..7
    const __nv_bfloat16* s;
    if (pl == 0)      s = Ah + (size_t)(row0 + r) * K + k0 + c * 8;
    else if (pl == 1) s = Al + (size_t)(row0 + r) * K + k0 + c * 8;
    else if (pl == 2) s = Bh + (size_t)(col0 + r) * K + k0 + c * 8;
    else              s = Bl + (size_t)(col0 + r) * K + k0 + c * 8;
    uint32_t d = sb + b * 65536 + pl * 16384 + r * 128 + ((c ^ (r & 7)) * 16);
    CP_ASYNC16(d, s);
  }
  CP_COMMIT();
}

template<int EPI, int OUTF, int OUTP>
__global__ __launch_bounds__(256) void mm_gemm(const __nv_bfloat16* __restrict__ Ap,
                                               const __nv_bfloat16* __restrict__ Bp,
                                               const float* __restrict__ bias,
                                               float* __restrict__ C,
                                               __nv_bfloat16* __restrict__ Cp,
                                               int M, int N, int K) {
  extern __shared__ char smem[];
  const uint32_t sb = smem_u32(smem);
  const int tid = threadIdx.x, wid = tid >> 5, lane = tid & 31;
  const int row0 = blockIdx.y * 128, col0 = blockIdx.x * 128;
  const size_t PA = (size_t)M * K, PB = (size_t)N * K;
  const __nv_bfloat16 *Ah = Ap, *Al = Ap + PA, *Bh = Bp, *Bl = Bp + PB;
  const int nc = K >> 6;

  const int wm = (wid >> 2) * 64, wn = (wid & 3) * 32;
  // ldmatrix per-lane rows
  const int rowa = wm + (lane & 15);                       // A fragment rows
  const int hiA  = lane >> 4;                              // k-half selector
  const int rowb = wn + (lane & 7) + ((lane >> 4) << 3);   // B fragment rows
  const int hiB  = (lane >> 3) & 1;                        // k-half selector

  float acc[4][4][4];
#pragma unroll
  for (int a = 0; a < 4; a++)
#pragma unroll
    for (int b = 0; b < 4; b++)
#pragma unroll
      for (int c = 0; c < 4; c++) acc[a][b][c] = 0.f;

  issue_chunk(sb, 0, Ah, Al, Bh, Bl, row0, col0, 0, K, tid);

  for (int ch = 0; ch < nc; ch++) {
    if (ch + 1 < nc) {
      issue_chunk(sb, (ch + 1) & 1, Ah, Al, Bh, Bl, row0, col0, (ch + 1) << 6, K, tid);
      asm volatile("cp.async.wait_group 1;" ::: "memory");
    } else {
      asm volatile("cp.async.wait_group 0;" ::: "memory");
    }
    __syncthreads();

    const uint32_t base = sb + (ch & 1) * 65536;
#pragma unroll
    for (int ks = 0; ks < 4; ks++) {
      uint32_t aH[4][4], aL[4][4];
#pragma unroll
      for (int mf = 0; mf < 4; mf++) {
        const int row = rowa + mf * 16;
        const uint32_t ad = base + row * 128 + (((ks * 2 + hiA) ^ (row & 7)) << 4);
        LDSM4(aH[mf][0], aH[mf][1], aH[mf][2], aH[mf][3], ad);
        LDSM4(aL[mf][0], aL[mf][1], aL[mf][2], aL[mf][3], ad + 16384);
      }
      uint32_t bH[4][2], bL[4][2];
#pragma unroll
      for (int nf2 = 0; nf2 < 2; nf2++) {
        const int row = rowb + nf2 * 16;
        const uint32_t bd = base + 32768 + row * 128 + (((ks * 2 + hiB) ^ (row & 7)) << 4);
        uint32_t r0, r1, r2, r3;
        LDSM4(r0, r1, r2, r3, bd);
        bH[nf2 * 2][0] = r0; bH[nf2 * 2][1] = r1;
        bH[nf2 * 2 + 1][0] = r2; bH[nf2 * 2 + 1][1] = r3;
        LDSM4(r0, r1, r2, r3, bd + 16384);
        bL[nf2 * 2][0] = r0; bL[nf2 * 2][1] = r1;
        bL[nf2 * 2 + 1][0] = r2; bL[nf2 * 2 + 1][1] = r3;
      }
#pragma unroll
      for (int mf = 0; mf < 4; mf++)
#pragma unroll
        for (int nf = 0; nf < 4; nf++) {
          MMA16816(acc[mf][nf], aH[mf][0], aH[mf][1], aH[mf][2], aH[mf][3],
                   bH[nf][0], bH[nf][1]);
          MMA16816(acc[mf][nf], aH[mf][0], aH[mf][1], aH[mf][2], aH[mf][3],
                   bL[nf][0], bL[nf][1]);
          MMA16816(acc[mf][nf], aL[mf][0], aL[mf][1], aL[mf][2], aL[mf][3],
                   bH[nf][0], bH[nf][1]);
        }
    }
    __syncthreads();
  }

  // epilogue: direct stores from accumulators
  const int er = row0 + wm + (lane >> 2);
  const int ec = col0 + wn + (lane & 3) * 2;
#pragma unroll
  for (int mf = 0; mf < 4; mf++) {
#pragma unroll
    for (int nf = 0; nf < 4; nf++) {
      const int cc = ec + nf * 8;
      float b0 = 0.f, b1 = 0.f;
      if (EPI >= 1) { b0 = bias[cc]; b1 = bias[cc + 1]; }
#pragma unroll
      for (int half = 0; half < 2; half++) {
        const int r = er + mf * 16 + half * 8;
        float v0 = acc[mf][nf][half * 2 + 0] + b0;
        float v1 = acc[mf][nf][half * 2 + 1] + b1;
        if (EPI == 2) { v0 = fmaxf(v0, 0.f); v1 = fmaxf(v1, 0.f); }
        const size_t go = (size_t)r * N + cc;
        if (OUTF) {
          float2 o; o.x = v0; o.y = v1;
          *(float2*)(C + go) = o;
        }
        if (OUTP) {
          __nv_bfloat16 h0, l0, h1, l1;
          split2(v0, h0, l0); split2(v1, h1, l1);
          *(uint32_t*)(Cp + go) = packb(h0, h1);
          *(uint32_t*)(Cp + (size_t)M * N + go) = packb(l0, l1);
        }
      }
    }
  }
}

// ---------------- causal flash attention (fp32 in, bf16 planes out) ----------------
__global__ __launch_bounds__(256) void attn_kernel(const float* __restrict__ qkv,
                                                   __nv_bfloat16* __restrict__ outP) {
  extern __shared__ float sm[];
  float* Qs = sm;
  float* Ks = sm + 4096;
  float* Vs = sm + 8192;
  float* Ps = sm + 12288;

  const int qt = blockIdx.x, h = blockIdx.y, b = blockIdx.z;
  const int tid = threadIdx.x, w = tid >> 5, lane = tid & 31;
  const size_t rowb = (size_t)b * kS;
  const int hoff = h * (3 * kHD);

  for (int idx = tid; idx < 1024; idx += 256) {
    int r = idx >> 4, d4 = (idx & 15) << 2;
    float4 v = *(const float4*)(qkv + (rowb + qt * 64 + r) * k3E + hoff + 64 + d4);
    *(float4*)&Qs[r * 64 + d4] = v;
  }

  float o0[8], o1[8], mrow[8], lrow[8];
#pragma unroll
  for (int r = 0; r < 8; r++) { o0[r] = 0.f; o1[r] = 0.f; mrow[r] = -1e30f; lrow[r] = 0.f; }
  const int q0 = qt * 64 + w * 8;
  float* Pw = Ps + w * 512;

  for (int kt = 0; kt <= qt; kt++) {
    __syncthreads();
    for (int idx = tid; idx < 1024; idx += 256) {
      int c = idx >> 4, d4 = (idx & 15) << 2;
      const float* src = qkv + (rowb + kt * 64 + c) * k3E + hoff + d4;
      float4 kv = *(const float4*)(src);
      Ks[(d4 + 0) * 64 + c] = kv.x; Ks[(d4 + 1) * 64 + c] = kv.y;
      Ks[(d4 + 2) * 64 + c] = kv.z; Ks[(d4 + 3) * 64 + c] = kv.w;
      float4 vv = *(const float4*)(src + 128);
      *(float4*)&Vs[c * 64 + d4] = vv;
    }
    __syncthreads();
    const bool diag = (kt == qt);
#pragma unroll 1
    for (int r = 0; r < 8; r++) {
      float s0 = 0.f, s1 = 0.f;
      const float* qr = Qs + (w * 8 + r) * 64;
#pragma unroll
      for (int d = 0; d < 64; d++) {
        float q = qr[d];
        s0 += q * Ks[d * 64 + lane];
        s1 += q * Ks[d * 64 + lane + 32];
      }
      s0 *= 0.125f; s1 *= 0.125f;
      if (diag) {
        const int qg = q0 + r;
        if (kt * 64 + lane      > qg) s0 = -1e30f;
        if (kt * 64 + lane + 32 > qg) s1 = -1e30f;
      }
      float mx = fmaxf(s0, s1);
#pragma unroll
      for (int off = 16; off; off >>= 1) mx = fmaxf(mx, __shfl_xor_sync(0xffffffffu, mx, off));
      const float mnew = fmaxf(mrow[r], mx);
      const float p0 = __expf(s0 - mnew), p1 = __expf(s1 - mnew);
      float rs = p0 + p1;
#pragma unroll
      for (int off = 16; off; off >>= 1) rs += __shfl_xor_sync(0xffffffffu, rs, off);
      const float corr = __expf(mrow[r] - mnew);
      mrow[r] = mnew; lrow[r] = lrow[r] * corr + rs;
      o0[r] *= corr; o1[r] *= corr;
      Pw[r * 64 + lane] = p0; Pw[r * 64 + lane + 32] = p1;
      __syncwarp();
#pragma unroll 8
      for (int c = 0; c < 64; c++) {
        const float p = Pw[r * 64 + c];
        o0[r] += p * Vs[c * 64 + lane];
        o1[r] += p * Vs[c * 64 + lane + 32];
      }
      __syncwarp();
    }
  }
  const size_t PL = (size_t)kM * kE;
#pragma unroll
  for (int r = 0; r < 8; r++) {
    const float inv = 1.f / lrow[r];
    const size_t o = (rowb + q0 + r) * kE + h * kHD;
    __nv_bfloat16 h0, l0, h1, l1;
    split2(o0[r] * inv, h0, l0);
    split2(o1[r] * inv, h1, l1);
    outP[o + lane] = h0;           outP[PL + o + lane] = l0;
    outP[o + lane + 32] = h1;      outP[PL + o + lane + 32] = l1;
  }
}

// ---------------- LayerNorm + residual (fp32 + planes) ----------------
__global__ __launch_bounds__(256) void ln_add_kernel(const float* __restrict__ x,
                                                     const float* __restrict__ gamma,
                                                     const float* __restrict__ beta,
                                                     float* __restrict__ h,
                                                     __nv_bfloat16* __restrict__ hP) {
  __shared__ float rs[8], rs2[8];
  const int row = blockIdx.x, tid = threadIdx.x;
  const int c = tid * 4;
  const size_t off = (size_t)row * kE + c;
  float4 xv = *(const float4*)(x + off);
  float s = xv.x + xv.y + xv.z + xv.w;
  float s2 = xv.x*xv.x + xv.y*xv.y + xv.z*xv.z + xv.w*xv.w;
#pragma unroll
  for (int o = 16; o; o >>= 1) {
    s  += __shfl_xor_sync(0xffffffffu, s, o);
    s2 += __shfl_xor_sync(0xffffffffu, s2, o);
  }
  if ((tid & 31) == 0) { rs[tid >> 5] = s; rs2[tid >> 5] = s2; }
  __syncthreads();
  float ts = 0.f, ts2 = 0.f;
#pragma unroll
  for (int i = 0; i < 8; i++) { ts += rs[i]; ts2 += rs2[i]; }
  const float mean = ts * (1.f / kE);
  const float var = ts2 * (1.f / kE) - mean * mean;
  const float rstd = rsqrtf(var + 1e-6f);
  float4 hv = *(const float4*)(h + off);
  float4 gv = *(const float4*)(gamma + c);
  float4 bv = *(const float4*)(beta + c);
  float4 o4;
  o4.x = (xv.x - mean) * rstd * gv.x + bv.x + hv.x;
  o4.y = (xv.y - mean) * rstd * gv.y + bv.y + hv.y;
  o4.z = (xv.z - mean) * rstd * gv.z + bv.z + hv.z;
  o4.w = (xv.w - mean) * rstd * gv.w + bv.w + hv.w;
  *(float4*)(h + off) = o4;
  __nv_bfloat16 h0,h1,h2,h3,l0,l1,l2,l3;
  split2(o4.x,h0,l0); split2(o4.y,h1,l1); split2(o4.z,h2,l2); split2(o4.w,h3,l3);
  uint2 hp; hp.x = packb(h0,h1); hp.y = packb(h2,h3);
  uint2 lp; lp.x = packb(l0,l1); lp.y = packb(l2,l3);
  *(uint2*)(hP + off) = hp;
  *(uint2*)(hP + (size_t)kM * kE + off) = lp;
}

// ---------------- launcher ----------------
extern "C" void kernel_launch(void* const* d_in, const int* in_sizes, int n_in,
                              void* d_out, int out_size) {
  (void)in_sizes; (void)n_in; (void)out_size;
  const void*  x   = d_in[0];
  const float* we  = (const float*)d_in[1];
  const float* pe  = (const float*)d_in[2];
  const float* KQV = (const float*)d_in[3];
  const float* WO  = (const float*)d_in[4];
  const float* Wup = (const float*)d_in[5];
  const float* bup = (const float*)d_in[6];
  const float* Wdn = (const float*)d_in[7];
  const float* bdn = (const float*)d_in[8];
  const float* g1  = (const float*)d_in[9];
  const float* b1  = (const float*)d_in[10];
  const float* g2  = (const float*)d_in[11];
  const float* b2  = (const float*)d_in[12];
  const float* ub  = (const float*)d_in[13];
  float* out = (float*)d_out;

  float *h, *qkvb, *tb;
  __nv_bfloat16 *hP, *attnP, *ffP, *wKQV, *wWO, *wUp, *wDn, *wWE;
  cudaGetSymbolAddress((void**)&h,     g_h);
  cudaGetSymbolAddress((void**)&qkvb,  g_qkv);
  cudaGetSymbolAddress((void**)&tb,    g_t);
  cudaGetSymbolAddress((void**)&hP,    g_hP);
  cudaGetSymbolAddress((void**)&attnP, g_attnP);
  cudaGetSymbolAddress((void**)&ffP,   g_ffP);
  cudaGetSymbolAddress((void**)&wKQV,  g_wKQV);
  cudaGetSymbolAddress((void**)&wWO,   g_wWO);
  cudaGetSymbolAddress((void**)&wUp,   g_wUp);
  cudaGetSymbolAddress((void**)&wDn,   g_wDn);
  cudaGetSymbolAddress((void**)&wWE,   g_wWE);

  cudaFuncSetAttribute(attn_kernel, cudaFuncAttributeMaxDynamicSharedMemorySize, 64 * 1024);
  cudaFuncSetAttribute(mm_gemm<0,1,0>, cudaFuncAttributeMaxDynamicSharedMemorySize, SMEM_MM);
  cudaFuncSetAttribute(mm_gemm<2,0,1>, cudaFuncAttributeMaxDynamicSharedMemorySize, SMEM_MM);
  cudaFuncSetAttribute(mm_gemm<1,1,0>, cudaFuncAttributeMaxDynamicSharedMemorySize, SMEM_MM);

  detect_x_kernel<<<1, 32>>>((const int*)x);
  embed_kernel<<<kM, 256>>>(x, we, pe);

  // weight prep (transpose + bf16x2 split)
  wsplitT_kernel<<<dim3(k3E/32, kE/32, kL), 256>>>(KQV, wKQV, kE, k3E);
  wsplitT_kernel<<<dim3(kE/32,  kE/32, kL), 256>>>(WO,  wWO,  kE, kE);
  wsplitT_kernel<<<dim3(kF/32,  kE/32, kL), 256>>>(Wup, wUp,  kE, kF);
  wsplitT_kernel<<<dim3(kE/32,  kF/32, kL), 256>>>(Wdn, wDn,  kF, kE);
  wsplit_kernel<<<(unsigned)(((size_t)kV*kE/4 + 255)/256), 256>>>(we, wWE, (size_t)kV*kE);

  for (int l = 0; l < kL; l++) {
    mm_gemm<0,1,0><<<dim3(k3E/128, kM/128), 256, SMEM_MM>>>(
        hP, wKQV + (size_t)l*2*k3E*kE, nullptr, qkvb, nullptr, kM, k3E, kE);
    attn_kernel<<<dim3(kS/64, kH, kB), 256, 64*1024>>>(qkvb, attnP);
    mm_gemm<0,1,0><<<dim3(kE/128, kM/128), 256, SMEM_MM>>>(
        attnP, wWO + (size_t)l*2*kE*kE, nullptr, tb, nullptr, kM, kE, kE);
    ln_add_kernel<<<kM, 256>>>(tb, g1 + l*kE, b1 + l*kE, h, hP);
    mm_gemm<2,0,1><<<dim3(kF/128, kM/128), 256, SMEM_MM>>>(
        hP, wUp + (size_t)l*2*kF*kE, bup + (size_t)l*kF, nullptr, ffP, kM, kF, kE);
    mm_gemm<1,1,0><<<dim3(kE/128, kM/128), 256, SMEM_MM>>>(
        ffP, wDn + (size_t)l*2*kE*kF, bdn + (size_t)l*kE, tb, nullptr, kM, kE, kF);
    ln_add_kernel<<<kM, 256>>>(tb, g2 + l*kE, b2 + l*kE, h, hP);
  }

  mm_gemm<1,1,0><<<dim3(kV/128, kM/128), 256, SMEM_MM>>>(
      hP, wWE, ub, out, nullptr, kM, kV, kE);
}

// round 13
// speedup vs baseline: 5.9453x; 1.9170x over previous
#include <cuda_runtime.h>
#include <cuda_bf16.h>
#include <cstdint>
#include <cstddef>

static constexpr int kS = 2048, kB = 2, kE = 1024, kH = 16, kHD = 64;
static constexpr int kF = 4096, kL = 4, kV = 32000;
static constexpr int kM = kB * kS;     // 4096
static constexpr int k3E = 3 * kE;     // 3072

// ---------------- scratch (no allocs allowed) ----------------
__device__ float g_h  [(size_t)kM * kE];
__device__ float g_t  [(size_t)kM * kE];
__device__ __nv_bfloat16 g_qkvP [2 * (size_t)kM * k3E];
__device__ __nv_bfloat16 g_hP   [2 * (size_t)kM * kE];
__device__ __nv_bfloat16 g_attnP[2 * (size_t)kM * kE];
__device__ __nv_bfloat16 g_ffP  [2 * (size_t)kM * kF];
__device__ __nv_bfloat16 g_wKQV [(size_t)kL * 2 * k3E * kE];
__device__ __nv_bfloat16 g_wWO  [(size_t)kL * 2 * kE  * kE];
__device__ __nv_bfloat16 g_wUp  [(size_t)kL * 2 * kF  * kE];
__device__ __nv_bfloat16 g_wDn  [(size_t)kL * 2 * kE  * kF];
__device__ __nv_bfloat16 g_wWE  [2 * (size_t)kV * kE];
__device__ int g_is64;

// ---------------- helpers (baseline PTX only) ----------------
__device__ __forceinline__ uint32_t smem_u32(const void* p) {
  uint32_t a;
  asm("{ .reg .u64 t; cvta.to.shared.u64 t, %1; cvt.u32.u64 %0, t; }" : "=r"(a) : "l"(p));
  return a;
}
#define CP_ASYNC16(d, s) \
  asm volatile("cp.async.cg.shared.global [%0], [%1], 16;" :: "r"(d), "l"(s) : "memory")
#define CP_COMMIT() asm volatile("cp.async.commit_group;" ::: "memory")
#define LDSM4(r0, r1, r2, r3, a) \
  asm volatile("ldmatrix.sync.aligned.m8n8.x4.shared.b16 {%0,%1,%2,%3},[%4];" \
               : "=r"(r0), "=r"(r1), "=r"(r2), "=r"(r3) : "r"(a))
#define MMA16816(c, a0, a1, a2, a3, b0, b1) \
  asm volatile("mma.sync.aligned.m16n8k16.row.col.f32.bf16.bf16.f32 " \
               "{%0,%1,%2,%3},{%4,%5,%6,%7},{%8,%9},{%0,%1,%2,%3};" \
               : "+f"((c)[0]), "+f"((c)[1]), "+f"((c)[2]), "+f"((c)[3]) \
               : "r"(a0), "r"(a1), "r"(a2), "r"(a3), "r"(b0), "r"(b1))

__device__ __forceinline__ void split2(float v, __nv_bfloat16& h, __nv_bfloat16& l) {
  h = __float2bfloat16(v);
  l = __float2bfloat16(v - __bfloat162float(h));
}
__device__ __forceinline__ uint32_t packb(__nv_bfloat16 a, __nv_bfloat16 b) {
  return (uint32_t)__bfloat16_as_ushort(a) | ((uint32_t)__bfloat16_as_ushort(b) << 16);
}
// split-pack two floats -> hi word + lo word
__device__ __forceinline__ void packPhl(float x, float y, uint32_t& hw, uint32_t& lw) {
  __nv_bfloat16 xh, xl, yh, yl;
  split2(x, xh, xl); split2(y, yh, yl);
  hw = packb(xh, yh); lw = packb(xl, yl);
}

// ---------------- token dtype detect ----------------
__global__ void detect_x_kernel(const int* __restrict__ xw) {
  if (threadIdx.x == 0 && blockIdx.x == 0) {
    int any = 0;
    for (int i = 1; i < 2048; i += 2) any |= xw[i];
    g_is64 = (any == 0) ? 1 : 0;
  }
}

// ---------------- weight prep ----------------
__global__ __launch_bounds__(256) void wsplitT_kernel(const float* __restrict__ src,
                                                      __nv_bfloat16* __restrict__ dst,
                                                      int Kd, int Nd) {
  __shared__ float t[32][33];
  const size_t lsz = (size_t)Kd * Nd;
  const float* S = src + (size_t)blockIdx.z * lsz;
  __nv_bfloat16* Hh = dst + (size_t)blockIdx.z * 2 * lsz;
  __nv_bfloat16* Ll = Hh + lsz;
  const int k0 = blockIdx.y * 32, n0 = blockIdx.x * 32;
  const int tx = threadIdx.x & 31, ty = threadIdx.x >> 5;
#pragma unroll
  for (int i = 0; i < 32; i += 8)
    t[ty + i][tx] = S[(size_t)(k0 + ty + i) * Nd + n0 + tx];
  __syncthreads();
#pragma unroll
  for (int i = 0; i < 32; i += 8) {
    float v = t[tx][ty + i];
    __nv_bfloat16 h, l; split2(v, h, l);
    size_t o = (size_t)(n0 + ty + i) * Kd + k0 + tx;
    Hh[o] = h; Ll[o] = l;
  }
}
__global__ __launch_bounds__(256) void wsplit_kernel(const float* __restrict__ s,
                                                     __nv_bfloat16* __restrict__ d, size_t n) {
  size_t i = ((size_t)blockIdx.x * 256 + threadIdx.x) * 4;
  if (i >= n) return;
  float4 v = *(const float4*)(s + i);
  __nv_bfloat16 h0,h1,h2,h3,l0,l1,l2,l3;
  split2(v.x,h0,l0); split2(v.y,h1,l1); split2(v.z,h2,l2); split2(v.w,h3,l3);
  uint2 hp; hp.x = packb(h0,h1); hp.y = packb(h2,h3);
  uint2 lp; lp.x = packb(l0,l1); lp.y = packb(l2,l3);
  *(uint2*)(d + i) = hp;
  *(uint2*)(d + n + i) = lp;
}

// ---------------- embedding (fp32 + planes) ----------------
__global__ __launch_bounds__(256) void embed_kernel(const void* __restrict__ x,
                                                    const float* __restrict__ we,
                                                    const float* __restrict__ pe) {
  const int row = blockIdx.x;
  const int s = row & (kS - 1);
  const long long tok = g_is64 ? ((const long long*)x)[row] : (long long)((const int*)x)[row];
  const int c = threadIdx.x * 4;
  float4 wv = *(const float4*)(we + (size_t)tok * kE + c);
  float4 pv = *(const float4*)(pe + (size_t)s * kE + c);
  float4 o;
  o.x = wv.x + pv.x; o.y = wv.y + pv.y; o.z = wv.z + pv.z; o.w = wv.w + pv.w;
  const size_t off = (size_t)row * kE + c;
  *(float4*)(g_h + off) = o;
  __nv_bfloat16 h0,h1,h2,h3,l0,l1,l2,l3;
  split2(o.x,h0,l0); split2(o.y,h1,l1); split2(o.z,h2,l2); split2(o.w,h3,l3);
  uint2 hp; hp.x = packb(h0,h1); hp.y = packb(h2,h3);
  uint2 lp; lp.x = packb(l0,l1); lp.y = packb(l2,l3);
  *(uint2*)(g_hP + off) = hp;
  *(uint2*)(g_hP + (size_t)kM * kE + off) = lp;
}

// ---------------- warp-MMA GEMM (bf16x2-split, 3-term, fp32 acc) ----------------
static constexpr int SMEM_MM = 2 * 65536;

__device__ __forceinline__ void issue_chunk(uint32_t sb, int b,
                                            const __nv_bfloat16* __restrict__ Ah,
                                            const __nv_bfloat16* __restrict__ Al,
                                            const __nv_bfloat16* __restrict__ Bh,
                                            const __nv_bfloat16* __restrict__ Bl,
                                            int row0, int col0, int k0, int K, int tid) {
#pragma unroll
  for (int i = 0; i < 16; i++) {
    int g = tid + i * 256;
    int pl = g >> 10;
    int j = g & 1023;
    int r = j >> 3, c = j & 7;
    const __nv_bfloat16* s;
    if (pl == 0)      s = Ah + (size_t)(row0 + r) * K + k0 + c * 8;
    else if (pl == 1) s = Al + (size_t)(row0 + r) * K + k0 + c * 8;
    else if (pl == 2) s = Bh + (size_t)(col0 + r) * K + k0 + c * 8;
    else              s = Bl + (size_t)(col0 + r) * K + k0 + c * 8;
    uint32_t d = sb + b * 65536 + pl * 16384 + r * 128 + ((c ^ (r & 7)) * 16);
    CP_ASYNC16(d, s);
  }
  CP_COMMIT();
}

template<int EPI, int OUTF, int OUTP>
__global__ __launch_bounds__(256) void mm_gemm(const __nv_bfloat16* __restrict__ Ap,
                                               const __nv_bfloat16* __restrict__ Bp,
                                               const float* __restrict__ bias,
                                               float* __restrict__ C,
                                               __nv_bfloat16* __restrict__ Cp,
                                               int M, int N, int K) {
  extern __shared__ char smem[];
  const uint32_t sb = smem_u32(smem);
  const int tid = threadIdx.x, wid = tid >> 5, lane = tid & 31;
  const int row0 = blockIdx.y * 128, col0 = blockIdx.x * 128;
  const size_t PA = (size_t)M * K, PB = (size_t)N * K;
  const __nv_bfloat16 *Ah = Ap, *Al = Ap + PA, *Bh = Bp, *Bl = Bp + PB;
  const int nc = K >> 6;

  const int wm = (wid >> 2) * 64, wn = (wid & 3) * 32;
  const int rowa = wm + (lane & 15);
  const int hiA  = lane >> 4;
  const int rowb = wn + (lane & 7) + ((lane >> 4) << 3);
  const int hiB  = (lane >> 3) & 1;

  float acc[4][4][4];
#pragma unroll
  for (int a = 0; a < 4; a++)
#pragma unroll
    for (int b = 0; b < 4; b++)
#pragma unroll
      for (int c = 0; c < 4; c++) acc[a][b][c] = 0.f;

  issue_chunk(sb, 0, Ah, Al, Bh, Bl, row0, col0, 0, K, tid);

  for (int ch = 0; ch < nc; ch++) {
    if (ch + 1 < nc) {
      issue_chunk(sb, (ch + 1) & 1, Ah, Al, Bh, Bl, row0, col0, (ch + 1) << 6, K, tid);
      asm volatile("cp.async.wait_group 1;" ::: "memory");
    } else {
      asm volatile("cp.async.wait_group 0;" ::: "memory");
    }
    __syncthreads();

    const uint32_t base = sb + (ch & 1) * 65536;
#pragma unroll
    for (int ks = 0; ks < 4; ks++) {
      uint32_t aH[4][4], aL[4][4];
#pragma unroll
      for (int mf = 0; mf < 4; mf++) {
        const int row = rowa + mf * 16;
        const uint32_t ad = base + row * 128 + (((ks * 2 + hiA) ^ (row & 7)) << 4);
        LDSM4(aH[mf][0], aH[mf][1], aH[mf][2], aH[mf][3], ad);
        LDSM4(aL[mf][0], aL[mf][1], aL[mf][2], aL[mf][3], ad + 16384);
      }
      uint32_t bH[4][2], bL[4][2];
#pragma unroll
      for (int nf2 = 0; nf2 < 2; nf2++) {
        const int row = rowb + nf2 * 16;
        const uint32_t bd = base + 32768 + row * 128 + (((ks * 2 + hiB) ^ (row & 7)) << 4);
        uint32_t r0, r1, r2, r3;
        LDSM4(r0, r1, r2, r3, bd);
        bH[nf2 * 2][0] = r0; bH[nf2 * 2][1] = r1;
        bH[nf2 * 2 + 1][0] = r2; bH[nf2 * 2 + 1][1] = r3;
        LDSM4(r0, r1, r2, r3, bd + 16384);
        bL[nf2 * 2][0] = r0; bL[nf2 * 2][1] = r1;
        bL[nf2 * 2 + 1][0] = r2; bL[nf2 * 2 + 1][1] = r3;
      }
#pragma unroll
      for (int mf = 0; mf < 4; mf++)
#pragma unroll
        for (int nf = 0; nf < 4; nf++) {
          MMA16816(acc[mf][nf], aH[mf][0], aH[mf][1], aH[mf][2], aH[mf][3],
                   bH[nf][0], bH[nf][1]);
          MMA16816(acc[mf][nf], aH[mf][0], aH[mf][1], aH[mf][2], aH[mf][3],
                   bL[nf][0], bL[nf][1]);
          MMA16816(acc[mf][nf], aL[mf][0], aL[mf][1], aL[mf][2], aL[mf][3],
                   bH[nf][0], bH[nf][1]);
        }
    }
    __syncthreads();
  }

  const int er = row0 + wm + (lane >> 2);
  const int ec = col0 + wn + (lane & 3) * 2;
#pragma unroll
  for (int mf = 0; mf < 4; mf++) {
#pragma unroll
    for (int nf = 0; nf < 4; nf++) {
      const int cc = ec + nf * 8;
      float b0 = 0.f, b1 = 0.f;
      if (EPI >= 1) { b0 = bias[cc]; b1 = bias[cc + 1]; }
#pragma unroll
      for (int half = 0; half < 2; half++) {
        const int r = er + mf * 16 + half * 8;
        float v0 = acc[mf][nf][half * 2 + 0] + b0;
        float v1 = acc[mf][nf][half * 2 + 1] + b1;
        if (EPI == 2) { v0 = fmaxf(v0, 0.f); v1 = fmaxf(v1, 0.f); }
        const size_t go = (size_t)r * N + cc;
        if (OUTF) {
          float2 o; o.x = v0; o.y = v1;
          *(float2*)(C + go) = o;
        }
        if (OUTP) {
          uint32_t hw, lw;
          packPhl(v0, v1, hw, lw);
          *(uint32_t*)(Cp + go) = hw;
          *(uint32_t*)(Cp + (size_t)M * N + go) = lw;
        }
      }
    }
  }
}

// ---------------- tensor-core causal flash attention ----------------
// Input: qkvP bf16 hi/lo planes [2][kM][k3E]; output: attnP planes [2][kM][kE].
// CTA: 128 q-rows of one (b,h); 8 warps x 16-row warp tiles; k-tiles of 64.
// Smem (64KB): Qh 16K | Ql 16K | Kh 8K | Kl 8K | Vth 8K | Vtl 8K  (swizzled 128B rows)
__global__ __launch_bounds__(256) void attn_mma_kernel(const __nv_bfloat16* __restrict__ qkvP,
                                                       __nv_bfloat16* __restrict__ outP) {
  extern __shared__ char sm[];
  const uint32_t sb = smem_u32(sm);
  const int qt = gridDim.x - 1 - blockIdx.x;  // heavy tiles first
  const int h = blockIdx.y, b = blockIdx.z;
  const int tid = threadIdx.x, w = tid >> 5, lane = tid & 31;
  const size_t rowb = (size_t)b * kS;
  const int hoff = h * 192;
  const size_t PL3 = (size_t)kM * k3E;
  const size_t PLE = (size_t)kM * kE;

  // load Q planes (128 x 64)
#pragma unroll
  for (int it = 0; it < 4; it++) {
    int idx = tid + it * 256;
    int r = idx >> 3, c16 = idx & 7;
    size_t g = (rowb + qt * 128 + r) * k3E + hoff + 64 + c16 * 8;
    uint4 vh = *(const uint4*)(qkvP + g);
    uint4 vl = *(const uint4*)(qkvP + PL3 + g);
    uint32_t d = r * 128 + (((c16 ^ (r & 7))) * 16);
    *(uint4*)(sm + d) = vh;
    *(uint4*)(sm + 16384 + d) = vl;
  }

  const int rw = w * 16;
  const int rA = rw + (lane & 15);
  const int hiA = lane >> 4;
  const int rB = (lane & 7) + ((lane >> 4) << 3);
  const int hiB = (lane >> 3) & 1;
  const int rr = lane >> 2;           // C-frag row within 16 (and +8)
  const int cc2 = (lane & 3) * 2;     // C-frag col pair

  float oacc[8][4];
#pragma unroll
  for (int nf = 0; nf < 8; nf++)
#pragma unroll
    for (int j = 0; j < 4; j++) oacc[nf][j] = 0.f;
  float m0 = -1e30f, m1 = -1e30f, l0 = 0.f, l1 = 0.f;

  const int grow0 = qt * 128 + rw + rr;   // global q row (and +8)
  const int nkt = 2 * qt + 2;

  for (int kt = 0; kt < nkt; kt++) {
    __syncthreads();
    // K planes (64 x 64)
#pragma unroll
    for (int it = 0; it < 2; it++) {
      int idx = tid + it * 256;
      int r = idx >> 3, c16 = idx & 7;
      size_t g = (rowb + kt * 64 + r) * k3E + hoff + c16 * 8;
      uint4 vh = *(const uint4*)(qkvP + g);
      uint4 vl = *(const uint4*)(qkvP + PL3 + g);
      uint32_t d = r * 128 + ((c16 ^ (r & 7)) * 16);
      *(uint4*)(sm + 32768 + d) = vh;
      *(uint4*)(sm + 40960 + d) = vl;
    }
    // V planes transposed: Vt[d][kpos]
#pragma unroll
    for (int it = 0; it < 2; it++) {
      int idx = tid + it * 256;
      int kp = idx >> 3, d8 = idx & 7;
      size_t g = (rowb + kt * 64 + kp) * k3E + hoff + 128 + d8 * 8;
      uint4 vh = *(const uint4*)(qkvP + g);
      uint4 vl = *(const uint4*)(qkvP + PL3 + g);
      const unsigned short* ph = (const unsigned short*)&vh;
      const unsigned short* pl = (const unsigned short*)&vl;
#pragma unroll
      for (int j = 0; j < 8; j++) {
        uint32_t off = (d8 * 8 + j) * 128 + (((kp >> 3) ^ j) * 16) + (kp & 7) * 2;
        *(unsigned short*)(sm + 49152 + off) = ph[j];
        *(unsigned short*)(sm + 57344 + off) = pl[j];
      }
    }
    __syncthreads();

    // ---- S = Q K^T (3-term split) ----
    float sacc[8][4];
#pragma unroll
    for (int nf = 0; nf < 8; nf++)
#pragma unroll
      for (int j = 0; j < 4; j++) sacc[nf][j] = 0.f;

#pragma unroll
    for (int ks = 0; ks < 4; ks++) {
      uint32_t qh[4], ql[4];
      const uint32_t ad = sb + rA * 128 + (((ks * 2 + hiA) ^ (rA & 7)) << 4);
      LDSM4(qh[0], qh[1], qh[2], qh[3], ad);
      LDSM4(ql[0], ql[1], ql[2], ql[3], ad + 16384);
#pragma unroll
      for (int nf16 = 0; nf16 < 4; nf16++) {
        const int row = nf16 * 16 + rB;
        const uint32_t bd = sb + 32768 + row * 128 + (((ks * 2 + hiB) ^ (row & 7)) << 4);
        uint32_t b0, b1, b2, b3, c0, c1, c2, c3;
        LDSM4(b0, b1, b2, b3, bd);
        LDSM4(c0, c1, c2, c3, bd + 8192);
        MMA16816(sacc[nf16 * 2],     qh[0], qh[1], qh[2], qh[3], b0, b1);
        MMA16816(sacc[nf16 * 2],     qh[0], qh[1], qh[2], qh[3], c0, c1);
        MMA16816(sacc[nf16 * 2],     ql[0], ql[1], ql[2], ql[3], b0, b1);
        MMA16816(sacc[nf16 * 2 + 1], qh[0], qh[1], qh[2], qh[3], b2, b3);
        MMA16816(sacc[nf16 * 2 + 1], qh[0], qh[1], qh[2], qh[3], c2, c3);
        MMA16816(sacc[nf16 * 2 + 1], ql[0], ql[1], ql[2], ql[3], b2, b3);
      }
    }

    // ---- online softmax in fragment layout ----
    const bool diag = (kt >= 2 * qt);
    float mx0 = -1e30f, mx1 = -1e30f;
#pragma unroll
    for (int nf = 0; nf < 8; nf++) {
      float s0 = sacc[nf][0] * 0.125f, s1 = sacc[nf][1] * 0.125f;
      float s2 = sacc[nf][2] * 0.125f, s3 = sacc[nf][3] * 0.125f;
      if (diag) {
        const int c0 = kt * 64 + nf * 8 + cc2;
        if (c0     > grow0)     s0 = -1e30f;
        if (c0 + 1 > grow0)     s1 = -1e30f;
        if (c0     > grow0 + 8) s2 = -1e30f;
        if (c0 + 1 > grow0 + 8) s3 = -1e30f;
      }
      sacc[nf][0] = s0; sacc[nf][1] = s1; sacc[nf][2] = s2; sacc[nf][3] = s3;
      mx0 = fmaxf(mx0, fmaxf(s0, s1));
      mx1 = fmaxf(mx1, fmaxf(s2, s3));
    }
    mx0 = fmaxf(mx0, __shfl_xor_sync(0xffffffffu, mx0, 1));
    mx0 = fmaxf(mx0, __shfl_xor_sync(0xffffffffu, mx0, 2));
    mx1 = fmaxf(mx1, __shfl_xor_sync(0xffffffffu, mx1, 1));
    mx1 = fmaxf(mx1, __shfl_xor_sync(0xffffffffu, mx1, 2));
    const float m0n = fmaxf(m0, mx0), m1n = fmaxf(m1, mx1);
    const float corr0 = __expf(m0 - m0n), corr1 = __expf(m1 - m1n);
    float rs0 = 0.f, rs1 = 0.f;
#pragma unroll
    for (int nf = 0; nf < 8; nf++) {
      float p0 = __expf(sacc[nf][0] - m0n);
      float p1 = __expf(sacc[nf][1] - m0n);
      float p2 = __expf(sacc[nf][2] - m1n);
      float p3 = __expf(sacc[nf][3] - m1n);
      sacc[nf][0] = p0; sacc[nf][1] = p1; sacc[nf][2] = p2; sacc[nf][3] = p3;
      rs0 += p0 + p1; rs1 += p2 + p3;
    }
    rs0 += __shfl_xor_sync(0xffffffffu, rs0, 1);
    rs0 += __shfl_xor_sync(0xffffffffu, rs0, 2);
    rs1 += __shfl_xor_sync(0xffffffffu, rs1, 1);
    rs1 += __shfl_xor_sync(0xffffffffu, rs1, 2);
    m0 = m0n; m1 = m1n;
    l0 = l0 * corr0 + rs0;
    l1 = l1 * corr1 + rs1;
#pragma unroll
    for (int nf = 0; nf < 8; nf++) {
      oacc[nf][0] *= corr0; oacc[nf][1] *= corr0;
      oacc[nf][2] *= corr1; oacc[nf][3] *= corr1;
    }

    // ---- O += P V (3-term split; P frags built from sacc in registers) ----
#pragma unroll
    for (int kg = 0; kg < 4; kg++) {
      uint32_t ah[4], al[4];
      packPhl(sacc[2 * kg][0],     sacc[2 * kg][1],     ah[0], al[0]);
      packPhl(sacc[2 * kg][2],     sacc[2 * kg][3],     ah[1], al[1]);
      packPhl(sacc[2 * kg + 1][0], sacc[2 * kg + 1][1], ah[2], al[2]);
      packPhl(sacc[2 * kg + 1][2], sacc[2 * kg + 1][3], ah[3], al[3]);
#pragma unroll
      for (int nf16 = 0; nf16 < 4; nf16++) {
        const int row = nf16 * 16 + rB;  // d index
        const uint32_t bd = sb + 49152 + row * 128 + (((kg * 2 + hiB) ^ (row & 7)) << 4);
        uint32_t b0, b1, b2, b3, c0, c1, c2, c3;
        LDSM4(b0, b1, b2, b3, bd);
        LDSM4(c0, c1, c2, c3, bd + 8192);
        MMA16816(oacc[nf16 * 2],     ah[0], ah[1], ah[2], ah[3], b0, b1);
        MMA16816(oacc[nf16 * 2],     ah[0], ah[1], ah[2], ah[3], c0, c1);
        MMA16816(oacc[nf16 * 2],     al[0], al[1], al[2], al[3], b0, b1);
        MMA16816(oacc[nf16 * 2 + 1], ah[0], ah[1], ah[2], ah[3], b2, b3);
        MMA16816(oacc[nf16 * 2 + 1], ah[0], ah[1], ah[2], ah[3], c2, c3);
        MMA16816(oacc[nf16 * 2 + 1], al[0], al[1], al[2], al[3], b2, b3);
      }
    }
  }

  // ---- epilogue: normalize + split-plane store ----
  const float inv0 = 1.f / l0, inv1 = 1.f / l1;
#pragma unroll
  for (int nf = 0; nf < 8; nf++) {
    const int d = h * 64 + nf * 8 + cc2;
    const size_t o0 = (rowb + grow0) * kE + d;
    const size_t o1 = (rowb + grow0 + 8) * kE + d;
    uint32_t hw, lw;
    packPhl(oacc[nf][0] * inv0, oacc[nf][1] * inv0, hw, lw);
    *(uint32_t*)(outP + o0) = hw;
    *(uint32_t*)(outP + PLE + o0) = lw;
    packPhl(oacc[nf][2] * inv1, oacc[nf][3] * inv1, hw, lw);
    *(uint32_t*)(outP + o1) = hw;
    *(uint32_t*)(outP + PLE + o1) = lw;
  }
}

// ---------------- LayerNorm + residual (fp32 + planes) ----------------
__global__ __launch_bounds__(256) void ln_add_kernel(const float* __restrict__ x,
                                                     const float* __restrict__ gamma,
                                                     const float* __restrict__ beta,
                                                     float* __restrict__ h,
                                                     __nv_bfloat16* __restrict__ hP) {
  __shared__ float rs[8], rs2[8];
  const int row = blockIdx.x, tid = threadIdx.x;
  const int c = tid * 4;
  const size_t off = (size_t)row * kE + c;
  float4 xv = *(const float4*)(x + off);
  float s = xv.x + xv.y + xv.z + xv.w;
  float s2 = xv.x*xv.x + xv.y*xv.y + xv.z*xv.z + xv.w*xv.w;
#pragma unroll
  for (int o = 16; o; o >>= 1) {
    s  += __shfl_xor_sync(0xffffffffu, s, o);
    s2 += __shfl_xor_sync(0xffffffffu, s2, o);
  }
  if ((tid & 31) == 0) { rs[tid >> 5] = s; rs2[tid >> 5] = s2; }
  __syncthreads();
  float ts = 0.f, ts2 = 0.f;
#pragma unroll
  for (int i = 0; i < 8; i++) { ts += rs[i]; ts2 += rs2[i]; }
  const float mean = ts * (1.f / kE);
  const float var = ts2 * (1.f / kE) - mean * mean;
  const float rstd = rsqrtf(var + 1e-6f);
  float4 hv = *(const float4*)(h + off);
  float4 gv = *(const float4*)(gamma + c);
  float4 bv = *(const float4*)(beta + c);
  float4 o4;
  o4.x = (xv.x - mean) * rstd * gv.x + bv.x + hv.x;
  o4.y = (xv.y - mean) * rstd * gv.y + bv.y + hv.y;
  o4.z = (xv.z - mean) * rstd * gv.z + bv.z + hv.z;
  o4.w = (xv.w - mean) * rstd * gv.w + bv.w + hv.w;
  *(float4*)(h + off) = o4;
  __nv_bfloat16 h0,h1,h2,h3,l0,l1,l2,l3;
  split2(o4.x,h0,l0); split2(o4.y,h1,l1); split2(o4.z,h2,l2); split2(o4.w,h3,l3);
  uint2 hp; hp.x = packb(h0,h1); hp.y = packb(h2,h3);
  uint2 lp; lp.x = packb(l0,l1); lp.y = packb(l2,l3);
  *(uint2*)(hP + off) = hp;
  *(uint2*)(hP + (size_t)kM * kE + off) = lp;
}

// ---------------- launcher ----------------
extern "C" void kernel_launch(void* const* d_in, const int* in_sizes, int n_in,
                              void* d_out, int out_size) {
  (void)in_sizes; (void)n_in; (void)out_size;
  const void*  x   = d_in[0];
  const float* we  = (const float*)d_in[1];
  const float* pe  = (const float*)d_in[2];
  const float* KQV = (const float*)d_in[3];
  const float* WO  = (const float*)d_in[4];
  const float* Wup = (const float*)d_in[5];
  const float* bup = (const float*)d_in[6];
  const float* Wdn = (const float*)d_in[7];
  const float* bdn = (const float*)d_in[8];
  const float* g1  = (const float*)d_in[9];
  const float* b1  = (const float*)d_in[10];
  const float* g2  = (const float*)d_in[11];
  const float* b2  = (const float*)d_in[12];
  const float* ub  = (const float*)d_in[13];
  float* out = (float*)d_out;

  float *h, *tb;
  __nv_bfloat16 *qkvP, *hP, *attnP, *ffP, *wKQV, *wWO, *wUp, *wDn, *wWE;
  cudaGetSymbolAddress((void**)&h,     g_h);
  cudaGetSymbolAddress((void**)&tb,    g_t);
  cudaGetSymbolAddress((void**)&qkvP,  g_qkvP);
  cudaGetSymbolAddress((void**)&hP,    g_hP);
  cudaGetSymbolAddress((void**)&attnP, g_attnP);
  cudaGetSymbolAddress((void**)&ffP,   g_ffP);
  cudaGetSymbolAddress((void**)&wKQV,  g_wKQV);
  cudaGetSymbolAddress((void**)&wWO,   g_wWO);
  cudaGetSymbolAddress((void**)&wUp,   g_wUp);
  cudaGetSymbolAddress((void**)&wDn,   g_wDn);
  cudaGetSymbolAddress((void**)&wWE,   g_wWE);

  cudaFuncSetAttribute(attn_mma_kernel, cudaFuncAttributeMaxDynamicSharedMemorySize, 64 * 1024);
  cudaFuncSetAttribute(mm_gemm<0,0,1>, cudaFuncAttributeMaxDynamicSharedMemorySize, SMEM_MM);
  cudaFuncSetAttribute(mm_gemm<0,1,0>, cudaFuncAttributeMaxDynamicSharedMemorySize, SMEM_MM);
  cudaFuncSetAttribute(mm_gemm<2,0,1>, cudaFuncAttributeMaxDynamicSharedMemorySize, SMEM_MM);
  cudaFuncSetAttribute(mm_gemm<1,1,0>, cudaFuncAttributeMaxDynamicSharedMemorySize, SMEM_MM);

  detect_x_kernel<<<1, 32>>>((const int*)x);
  embed_kernel<<<kM, 256>>>(x, we, pe);

  wsplitT_kernel<<<dim3(k3E/32, kE/32, kL), 256>>>(KQV, wKQV, kE, k3E);
  wsplitT_kernel<<<dim3(kE/32,  kE/32, kL), 256>>>(WO,  wWO,  kE, kE);
  wsplitT_kernel<<<dim3(kF/32,  kE/32, kL), 256>>>(Wup, wUp,  kE, kF);
  wsplitT_kernel<<<dim3(kE/32,  kF/32, kL), 256>>>(Wdn, wDn,  kF, kE);
  wsplit_kernel<<<(unsigned)(((size_t)kV*kE/4 + 255)/256), 256>>>(we, wWE, (size_t)kV*kE);

  for (int l = 0; l < kL; l++) {
    // qkv planes = hP @ KQV[l]
    mm_gemm<0,0,1><<<dim3(k3E/128, kM/128), 256, SMEM_MM>>>(
        hP, wKQV + (size_t)l*2*k3E*kE, nullptr, nullptr, qkvP, kM, k3E, kE);
    // attention (tensor cores)
    attn_mma_kernel<<<dim3(kS/128, kH, kB), 256, 64*1024>>>(qkvP, attnP);
    // t = attn @ WO[l]
    mm_gemm<0,1,0><<<dim3(kE/128, kM/128), 256, SMEM_MM>>>(
        attnP, wWO + (size_t)l*2*kE*kE, nullptr, tb, nullptr, kM, kE, kE);
    ln_add_kernel<<<kM, 256>>>(tb, g1 + l*kE, b1 + l*kE, h, hP);
    // ff planes = relu(h @ Wup + bup)
    mm_gemm<2,0,1><<<dim3(kF/128, kM/128), 256, SMEM_MM>>>(
        hP, wUp + (size_t)l*2*kF*kE, bup + (size_t)l*kF, nullptr, ffP, kM, kF, kE);
    // t = ff @ Wdn + bdn
    mm_gemm<1,1,0><<<dim3(kE/128, kM/128), 256, SMEM_MM>>>(
        ffP, wDn + (size_t)l*2*kE*kF, bdn + (size_t)l*kE, tb, nullptr, kM, kE, kF);
    ln_add_kernel<<<kM, 256>>>(tb, g2 + l*kE, b2 + l*kE, h, hP);
  }

  mm_gemm<1,1,0><<<dim3(kV/128, kM/128), 256, SMEM_MM>>>(
      hP, wWE, ub, out, nullptr, kM, kV, kE);
}